// round 2
// baseline (speedup 1.0000x reference)
#include <cuda_runtime.h>

#define B_ 64
#define R_ 32
#define N_ 16384
#define D_ 64
#define O_ 8
#define SPLIT_ 4

// __device__ scratch (no allocations allowed)
__device__ int   g_mask_kind;            // 0 = uint8/bool, 1 = int32 0/1, 2 = float32 0.0/1.0
__device__ __align__(16) float g_s[B_][D_];   // masked sum of normalized context rows
__device__ float g_nvalid[B_];

// ---------------------------------------------------------------------------
// Kernel 1: probe mask dtype from raw bits + zero accumulators.
// Single block, deterministic, runs every replay.
// ---------------------------------------------------------------------------
__global__ void ssfw_probe_zero(const void* __restrict__ adj,
                                const void* __restrict__ two) {
    const int PROBE = 8192;  // 8192 u32 = 32 KB, safe even if masks are 1-byte (1 MB buffer)
    __shared__ int sh_other, sh_f32, sh_one;
    if (threadIdx.x == 0) { sh_other = 0; sh_f32 = 0; sh_one = 0; }
    __syncthreads();

    int has_other = 0, has_f = 0, has_one = 0;
    const unsigned* a = (const unsigned*)adj;
    const unsigned* t = (const unsigned*)two;
    for (int i = threadIdx.x; i < PROBE; i += blockDim.x) {
        unsigned v0 = a[i], v1 = t[i];
        #pragma unroll
        for (int k = 0; k < 2; k++) {
            unsigned v = k ? v1 : v0;
            if (v == 1u)               has_one = 1;
            else if (v == 0x3F800000u) has_f   = 1;
            else if (v != 0u)          has_other = 1;  // packed bytes -> values like 0x100, 0x10001...
        }
    }
    if (has_other) atomicOr(&sh_other, 1);
    if (has_f)     atomicOr(&sh_f32, 1);
    if (has_one)   atomicOr(&sh_one, 1);

    // zero global accumulators (graph replays need fresh zeros every launch)
    float* gs = &g_s[0][0];
    for (int i = threadIdx.x; i < B_ * D_; i += blockDim.x) gs[i] = 0.0f;
    for (int i = threadIdx.x; i < B_; i += blockDim.x) g_nvalid[i] = 0.0f;

    __syncthreads();
    if (threadIdx.x == 0) {
        int kind;
        if (sh_other)    kind = 0;   // raw bytes (bool/uint8/int8)
        else if (sh_f32) kind = 2;   // float32 0.0/1.0
        else             kind = 1;   // int32 0/1 (also the all-zero fallback)
        g_mask_kind = kind;
    }
}

// ---------------------------------------------------------------------------
// Kernel 2: masked reduction.  grid = (B, SPLIT), block = 256.
// Only valid (~0.74%) context rows are ever read from HBM.
// ---------------------------------------------------------------------------
__global__ __launch_bounds__(256)
void ssfw_reduce(const float* __restrict__ hctx,
                 const int*   __restrict__ center_o,
                 const int*   __restrict__ o_types,
                 const void*  __restrict__ adj,
                 const void*  __restrict__ two) {
    const int b    = blockIdx.x;
    const int part = blockIdx.y;
    const int tid  = threadIdx.x;
    const int n0   = part * (N_ / SPLIT_);
    const int n1   = n0 + (N_ / SPLIT_);

    __shared__ float s_acc[D_];
    __shared__ int   s_cnt;
    for (int d = tid; d < D_; d += blockDim.x) s_acc[d] = 0.0f;
    if (tid == 0) s_cnt = 0;
    __syncthreads();

    const int kind = g_mask_kind;
    const int ctr  = center_o[b];
    const int* ot  = o_types + (long long)b * N_;
    int localc = 0;

    for (int n = n0 + tid; n < n1; n += blockDim.x) {
        long long mi = (long long)b * N_ + n;
        bool c;
        if (kind == 0) {
            c = (((const unsigned char*)adj)[mi] | ((const unsigned char*)two)[mi]) != 0;
        } else if (kind == 1) {
            c = (((const int*)adj)[mi] | ((const int*)two)[mi]) != 0;
        } else {
            c = (((const float*)adj)[mi] != 0.0f) || (((const float*)two)[mi] != 0.0f);
        }
        if (c && ot[n] == ctr) {
            localc++;
            const float4* row = (const float4*)(hctx + ((long long)b * N_ + n) * D_);
            float4 v[16];
            float sq = 0.0f;
            #pragma unroll
            for (int i = 0; i < 16; i++) {
                v[i] = row[i];
                sq += v[i].x * v[i].x + v[i].y * v[i].y + v[i].z * v[i].z + v[i].w * v[i].w;
            }
            float rn = rsqrtf(fmaxf(sq, 1e-12f));
            #pragma unroll
            for (int i = 0; i < 16; i++) {
                atomicAdd(&s_acc[4 * i + 0], v[i].x * rn);
                atomicAdd(&s_acc[4 * i + 1], v[i].y * rn);
                atomicAdd(&s_acc[4 * i + 2], v[i].z * rn);
                atomicAdd(&s_acc[4 * i + 3], v[i].w * rn);
            }
        }
    }
    if (localc) atomicAdd(&s_cnt, localc);
    __syncthreads();

    for (int d = tid; d < D_; d += blockDim.x) {
        float val = s_acc[d];
        if (val != 0.0f) atomicAdd(&g_s[b][d], val);
        else             atomicAdd(&g_s[b][d], 0.0f);   // keep deterministic work; cost trivial
    }
    if (tid == 0 && s_cnt) atomicAdd(&g_nvalid[b], (float)s_cnt);
}

// ---------------------------------------------------------------------------
// Kernel 3: finalize.  grid = B, block = 1024 (warp per r).
// ---------------------------------------------------------------------------
__global__ __launch_bounds__(1024)
void ssfw_finalize(const float* __restrict__ l_local,
                   const float* __restrict__ lambda_so,
                   const int*   __restrict__ center_o,
                   float*       __restrict__ out) {
    const int b    = blockIdx.x;
    const int r    = threadIdx.x >> 5;
    const int lane = threadIdx.x & 31;

    const float2* lrow = (const float2*)(l_local + ((long long)b * R_ + r) * D_);
    float2 lv = lrow[lane];
    float2 sv = *(const float2*)(&g_s[b][lane * 2]);

    float sq = lv.x * lv.x + lv.y * lv.y;
    float dp = lv.x * sv.x + lv.y * sv.y;
    #pragma unroll
    for (int o = 16; o > 0; o >>= 1) {
        sq += __shfl_xor_sync(0xffffffffu, sq, o);
        dp += __shfl_xor_sync(0xffffffffu, dp, o);
    }
    if (lane == 0) {
        float nv   = g_nvalid[b];
        float rinv = rsqrtf(fmaxf(sq, 1e-12f));
        float avg  = rinv * dp / fmaxf(nv, 1e-9f);
        float lam  = lambda_so[r * O_ + center_o[b]];
        float w    = fmaxf(lam / fmaxf(nv, 1.0f), 0.0f) * (1.0f - avg);
        out[b * R_ + r] = w;
    }
}

// ---------------------------------------------------------------------------
// Launch contract
// Inputs (metadata order): 0 l_local [B,R,D] f32, 1 h_context [B,N,D] f32,
// 2 lambda_so [R,O] f32, 3 center_o [B] i32, 4 o_types [B,N] i32,
// 5 adj_mask [B,N] bool, 6 two_hop_mask [B,N] bool.  Output [B,R] f32.
// ---------------------------------------------------------------------------
extern "C" void kernel_launch(void* const* d_in, const int* in_sizes, int n_in,
                              void* d_out, int out_size) {
    const float* l_local   = (const float*)d_in[0];
    const float* h_context = (const float*)d_in[1];
    const float* lambda_so = (const float*)d_in[2];
    const int*   center_o  = (const int*)d_in[3];
    const int*   o_types   = (const int*)d_in[4];
    const void*  adj_mask  = d_in[5];
    const void*  two_mask  = d_in[6];
    float*       out       = (float*)d_out;

    ssfw_probe_zero<<<1, 256>>>(adj_mask, two_mask);
    ssfw_reduce<<<dim3(B_, SPLIT_), 256>>>(h_context, center_o, o_types, adj_mask, two_mask);
    ssfw_finalize<<<B_, 1024>>>(l_local, lambda_so, center_o, out);
}

// round 3
// speedup vs baseline: 1.3844x; 1.3844x over previous
#include <cuda_runtime.h>

#define B_ 64
#define R_ 32
#define N_ 16384
#define D_ 64
#define O_ 8
#define SPLIT_ 16
#define CHUNK_ (N_ / SPLIT_)   /* 1024 = 256 threads * 4 */

// Plain-store partials: every slot written every launch -> no zeroing pass needed.
__device__ __align__(16) float g_part[B_][SPLIT_][D_];
__device__ float g_cnt[B_][SPLIT_];

// ---------------------------------------------------------------------------
// Kernel 1: masked reduction with inline mask-dtype probe.
// grid = (B, SPLIT), block = 256. Each thread owns 4 consecutive n.
// Only valid (~0.74%) context rows are ever read from HBM.
// ---------------------------------------------------------------------------
__global__ __launch_bounds__(256)
void ssfw_reduce(const float* __restrict__ hctx,
                 const int*   __restrict__ center_o,
                 const int*   __restrict__ o_types,
                 const void*  __restrict__ adj,
                 const void*  __restrict__ two) {
    const int b    = blockIdx.x;
    const int part = blockIdx.y;
    const int tid  = threadIdx.x;

    __shared__ int   sh_flags;          // bit0 = "other" (bytes), bit1 = f32 pattern
    __shared__ float s_acc[D_];
    __shared__ int   s_cnt;
    if (tid == 0) { sh_flags = 0; s_cnt = 0; }
    if (tid < D_) s_acc[tid] = 0.0f;
    __syncthreads();

    // --- inline probe: classify mask dtype from first 2KB of each array ---
    // (deterministic, identical in every block; L2-hot after first wave)
    {
        const unsigned* a = (const unsigned*)adj;
        const unsigned* t = (const unsigned*)two;
        int fl = 0;
        #pragma unroll
        for (int k = 0; k < 2; k++) {
            unsigned v0 = a[tid + k * 256];
            unsigned v1 = t[tid + k * 256];
            #pragma unroll
            for (int j = 0; j < 2; j++) {
                unsigned v = j ? v1 : v0;
                if (v == 0x3F800000u)            fl |= 2;  // 1.0f
                else if (v != 0u && v != 1u)     fl |= 1;  // packed bytes / anything else
            }
        }
        if (fl) atomicOr(&sh_flags, fl);
    }
    __syncthreads();
    const int flags = sh_flags;
    const int kind  = (flags & 1) ? 0 : ((flags & 2) ? 2 : 1);  // 0=u8, 1=i32, 2=f32

    // --- vectorized mask evaluation: 4 consecutive n per thread ---
    const int       n_base = part * CHUNK_ + tid * 4;
    const long long mi     = (long long)b * N_ + n_base;
    unsigned m[4];
    if (kind == 1) {
        uint4 va = *(const uint4*)((const int*)adj + mi);
        uint4 vt = *(const uint4*)((const int*)two + mi);
        m[0] = va.x | vt.x; m[1] = va.y | vt.y;
        m[2] = va.z | vt.z; m[3] = va.w | vt.w;
    } else if (kind == 0) {
        unsigned va = *(const unsigned*)((const unsigned char*)adj + mi);
        unsigned vt = *(const unsigned*)((const unsigned char*)two + mi);
        unsigned u  = va | vt;
        m[0] = u & 0xffu; m[1] = (u >> 8) & 0xffu;
        m[2] = (u >> 16) & 0xffu; m[3] = u >> 24;
    } else {
        float4 va = *(const float4*)((const float*)adj + mi);
        float4 vt = *(const float4*)((const float*)two + mi);
        m[0] = (va.x != 0.0f) || (vt.x != 0.0f);
        m[1] = (va.y != 0.0f) || (vt.y != 0.0f);
        m[2] = (va.z != 0.0f) || (vt.z != 0.0f);
        m[3] = (va.w != 0.0f) || (vt.w != 0.0f);
    }

    int localc = 0;
    if (m[0] | m[1] | m[2] | m[3]) {
        const int  ctr = center_o[b];
        const int4 ov  = *(const int4*)(o_types + mi);
        const int  oo[4] = { ov.x, ov.y, ov.z, ov.w };
        #pragma unroll
        for (int j = 0; j < 4; j++) {
            if (m[j] && oo[j] == ctr) {
                localc++;
                const float4* row = (const float4*)(hctx + (mi + j) * D_);
                float4 v[16];
                float sq = 0.0f;
                #pragma unroll
                for (int i = 0; i < 16; i++) {
                    v[i] = row[i];
                    sq += v[i].x * v[i].x + v[i].y * v[i].y
                        + v[i].z * v[i].z + v[i].w * v[i].w;
                }
                float rn = rsqrtf(fmaxf(sq, 1e-12f));
                #pragma unroll
                for (int i = 0; i < 16; i++) {
                    atomicAdd(&s_acc[4 * i + 0], v[i].x * rn);
                    atomicAdd(&s_acc[4 * i + 1], v[i].y * rn);
                    atomicAdd(&s_acc[4 * i + 2], v[i].z * rn);
                    atomicAdd(&s_acc[4 * i + 3], v[i].w * rn);
                }
            }
        }
    }
    if (localc) atomicAdd(&s_cnt, localc);
    __syncthreads();

    // plain partial stores -> no global zeroing required
    if (tid < D_) g_part[b][part][tid] = s_acc[tid];
    if (tid == 0) g_cnt[b][part] = (float)s_cnt;
}

// ---------------------------------------------------------------------------
// Kernel 2: finalize.  grid = B, block = 1024 (one warp per r).
// ---------------------------------------------------------------------------
__global__ __launch_bounds__(1024)
void ssfw_finalize(const float* __restrict__ l_local,
                   const float* __restrict__ lambda_so,
                   const int*   __restrict__ center_o,
                   float*       __restrict__ out) {
    const int b    = blockIdx.x;
    const int r    = threadIdx.x >> 5;
    const int lane = threadIdx.x & 31;

    // sum partials for this lane's two dims (L2-hot)
    float2 sv = make_float2(0.0f, 0.0f);
    #pragma unroll
    for (int p = 0; p < SPLIT_; p++) {
        float2 v = *(const float2*)(&g_part[b][p][lane * 2]);
        sv.x += v.x; sv.y += v.y;
    }

    const float2* lrow = (const float2*)(l_local + ((long long)b * R_ + r) * D_);
    float2 lv = lrow[lane];

    float sq = lv.x * lv.x + lv.y * lv.y;
    float dp = lv.x * sv.x + lv.y * sv.y;
    #pragma unroll
    for (int o = 16; o > 0; o >>= 1) {
        sq += __shfl_xor_sync(0xffffffffu, sq, o);
        dp += __shfl_xor_sync(0xffffffffu, dp, o);
    }

    if (lane == 0) {
        float nv = 0.0f;
        #pragma unroll
        for (int p = 0; p < SPLIT_; p++) nv += g_cnt[b][p];
        float rinv = rsqrtf(fmaxf(sq, 1e-12f));
        float avg  = rinv * dp / fmaxf(nv, 1e-9f);
        float lam  = lambda_so[r * O_ + center_o[b]];
        float w    = fmaxf(lam / fmaxf(nv, 1.0f), 0.0f) * (1.0f - avg);
        out[b * R_ + r] = w;
    }
}

// ---------------------------------------------------------------------------
// Launch contract
// Inputs (metadata order): 0 l_local [B,R,D] f32, 1 h_context [B,N,D] f32,
// 2 lambda_so [R,O] f32, 3 center_o [B] i32, 4 o_types [B,N] i32,
// 5 adj_mask [B,N] bool, 6 two_hop_mask [B,N] bool.  Output [B,R] f32.
// ---------------------------------------------------------------------------
extern "C" void kernel_launch(void* const* d_in, const int* in_sizes, int n_in,
                              void* d_out, int out_size) {
    const float* l_local   = (const float*)d_in[0];
    const float* h_context = (const float*)d_in[1];
    const float* lambda_so = (const float*)d_in[2];
    const int*   center_o  = (const int*)d_in[3];
    const int*   o_types   = (const int*)d_in[4];
    const void*  adj_mask  = d_in[5];
    const void*  two_mask  = d_in[6];
    float*       out       = (float*)d_out;

    ssfw_reduce<<<dim3(B_, SPLIT_), 256>>>(h_context, center_o, o_types, adj_mask, two_mask);
    ssfw_finalize<<<B_, 1024>>>(l_local, lambda_so, center_o, out);
}